// round 1
// baseline (speedup 1.0000x reference)
#include <cuda_runtime.h>
#include <cuda_bf16.h>
#include <math.h>

#define BN     8192      // samples
#define ZD     128       // feature dim
#define NC     62        // classes
#define NP     93        // proxies
#define NA     2730      // anchors: 0,3,...,8187
#define EPSV   1e-6f
#define EPS2T  1.28e-10f // ZD * EPS^2
#define NEG_INF (-INFINITY)

// ---------------- persistent scratch (device globals; no allocs) -------------
__device__ float g_prx[NP * ZD];     // normalized proxies
__device__ float g_pss[NP];          // sum(prx^2) per proxy row
__device__ float g_psum[NP];         // sum(prx) per proxy row
__device__ float g_zz[BN];           // sum(z^2) per sample
__device__ float g_zs[BN];           // sum(z)  per sample
__device__ int   g_yrel[BN];
__device__ int   g_cnt[NC];
__device__ int   g_cur[NC];
__device__ int   g_start[NC + 1];
__device__ int   g_clsidx[BN];
__device__ int   g_pidx[NA];
__device__ int   g_jp[NA];
__device__ float g_Dp[NA];
__device__ float g_loss[NA];

// ---------------- helpers ---------------------------------------------------
__device__ __forceinline__ float warp_sum(float v) {
#pragma unroll
    for (int o = 16; o; o >>= 1) v += __shfl_xor_sync(0xffffffffu, v, o);
    return v;
}

// block of 128 threads, deterministic
__device__ __forceinline__ float block_sum_128(float v, float* sbuf) {
    int lane = threadIdx.x & 31, w = threadIdx.x >> 5;
    v = warp_sum(v);
    if (lane == 0) sbuf[w] = v;
    __syncthreads();
    float r = sbuf[0] + sbuf[1] + sbuf[2] + sbuf[3];
    __syncthreads();
    return r;
}

__device__ __forceinline__ float block_max_128(float v, float* sbuf) {
    int lane = threadIdx.x & 31, w = threadIdx.x >> 5;
#pragma unroll
    for (int o = 16; o; o >>= 1) v = fmaxf(v, __shfl_xor_sync(0xffffffffu, v, o));
    if (lane == 0) sbuf[w] = v;
    __syncthreads();
    float r = fmaxf(fmaxf(sbuf[0], sbuf[1]), fmaxf(sbuf[2], sbuf[3]));
    __syncthreads();
    return r;
}

// ---------------- K1: normalize proxies + zero counters ----------------------
// grid: NP blocks x 128 threads
__global__ void k_prox(const float* __restrict__ proxies) {
    __shared__ float sbuf[4];
    int b = blockIdx.x, t = threadIdx.x;
    if (b == 0 && t < NC) { g_cnt[t] = 0; g_cur[t] = 0; }
    float v = proxies[b * ZD + t];
    float ss = block_sum_128(v * v, sbuf);
    float denom = fmaxf(sqrtf(ss), 1e-12f);
    float o = v / denom;
    g_prx[b * ZD + t] = o;
    float so  = block_sum_128(o, sbuf);
    float so2 = block_sum_128(o * o, sbuf);
    if (t == 0) { g_psum[b] = so; g_pss[b] = so2; }
}

// ---------------- K2: per-sample stats + y_rel + class histogram -------------
// grid: 64 blocks x 256 threads  (512 warps, each warp handles 16 rows)
__global__ void k_zstats(const float* __restrict__ z,
                         const int* __restrict__ y_idx,
                         const int* __restrict__ y_map) {
    int gw = (blockIdx.x * blockDim.x + threadIdx.x) >> 5;
    int nw = (gridDim.x * blockDim.x) >> 5;
    int lane = threadIdx.x & 31;
    for (int row = gw; row < BN; row += nw) {
        float s = 0.f, ss = 0.f;
        const float* zr = z + (size_t)row * ZD;
#pragma unroll
        for (int k = lane; k < ZD; k += 32) { float v = zr[k]; s += v; ss += v * v; }
        s = warp_sum(s); ss = warp_sum(ss);
        if (lane == 0) {
            g_zs[row] = s; g_zz[row] = ss;
            int yi = y_idx[row];
            int r = 0;
            for (int k = 0; k < NC; k++) { if (y_map[k] == yi) { r = k; break; } }
            g_yrel[row] = r;
            atomicAdd(&g_cnt[r], 1);
        }
    }
}

// ---------------- K3: exclusive scan + scatter into class lists --------------
// grid: 1 block x 1024 threads
__global__ void k_scan_scatter() {
    __shared__ int sstart[NC + 1];
    if (threadIdx.x == 0) {
        int acc = 0;
        for (int c = 0; c < NC; c++) { sstart[c] = acc; acc += g_cnt[c]; }
        sstart[NC] = acc;
        for (int c = 0; c <= NC; c++) g_start[c] = sstart[c];
    }
    __syncthreads();
    for (int j = threadIdx.x; j < BN; j += blockDim.x) {
        int c = g_yrel[j];
        int pos = atomicAdd(&g_cur[c], 1);
        g_clsidx[sstart[c] + pos] = j;
    }
}

// ---------------- K4: nearest proxy per anchor -------------------------------
// grid: NA blocks x 128 threads
__global__ void k_nearest(const float* __restrict__ z) {
    int a = 3 * blockIdx.x, t = threadIdx.x;
    __shared__ float za[ZD];
    __shared__ float sv[128];
    __shared__ int   si[128];
    za[t] = z[(size_t)a * ZD + t];
    __syncthreads();
    float best = INFINITY; int bidx = 0x7fffffff;
    if (t < NP) {
        const float* pr = &g_prx[t * ZD];
        float dot = 0.f;
#pragma unroll 8
        for (int k = 0; k < ZD; k++) dot = fmaf(za[k], pr[k], dot);
        float d2 = g_zz[a] + g_pss[t] - 2.f * dot
                 + 2.f * EPSV * (g_zs[a] - g_psum[t]) + EPS2T;
        best = sqrtf(fmaxf(d2, 0.f));
        bidx = t;
    }
    sv[t] = best; si[t] = bidx;
    __syncthreads();
#pragma unroll
    for (int o = 64; o > 0; o >>= 1) {
        if (t < o) {
            float v2 = sv[t + o]; int i2 = si[t + o];
            if (v2 < sv[t] || (v2 == sv[t] && i2 < si[t])) { sv[t] = v2; si[t] = i2; }
        }
        __syncthreads();
    }
    if (t == 0) g_pidx[blockIdx.x] = si[0];
}

// ---------------- K5: hardest positive (masked argmax, sparse) ---------------
// grid: NA blocks x 128 threads (4 warps; warp-cooperative dot per candidate)
__global__ void k_hardpos(const float* __restrict__ z) {
    int i = blockIdx.x, a = 3 * i, t = threadIdx.x;
    int lane = t & 31, w = t >> 5;
    __shared__ float pr[ZD];
    __shared__ float s_pss, s_psum;
    __shared__ float wv[4];
    __shared__ int   wj[4];
    int p = g_pidx[i];
    pr[t] = g_prx[p * ZD + t];
    if (t == 0) { s_pss = g_pss[p]; s_psum = g_psum[p]; }
    __syncthreads();
    int c = g_yrel[a];
    int s0 = g_start[c], s1 = g_start[c + 1];
    float bestv = NEG_INF; int bestj = 0x7fffffff;
    for (int idx = s0 + w; idx < s1; idx += 4) {
        int j = g_clsidx[idx];
        if (j < a) continue;           // suffix mask (warp-uniform)
        const float* zr = z + (size_t)j * ZD;
        float dot = 0.f;
#pragma unroll
        for (int k = lane; k < ZD; k += 32) dot = fmaf(pr[k], zr[k], dot);
        dot = warp_sum(dot);
        float d2 = s_pss + g_zz[j] - 2.f * dot
                 + 2.f * EPSV * (s_psum - g_zs[j]) + EPS2T;
        float d = sqrtf(fmaxf(d2, 0.f));
        if (d > bestv || (d == bestv && j < bestj)) { bestv = d; bestj = j; }
    }
    if (lane == 0) { wv[w] = bestv; wj[w] = bestj; }
    __syncthreads();
    if (t == 0) {
        float bv = wv[0]; int bj = wj[0];
#pragma unroll
        for (int q = 1; q < 4; q++)
            if (wv[q] > bv || (wv[q] == bv && wj[q] < bj)) { bv = wv[q]; bj = wj[q]; }
        g_jp[i] = bj; g_Dp[i] = bv;
    }
}

// ---------------- K6: D_n + logsumexp + per-anchor loss ----------------------
// grid: NA blocks x 128 threads
__global__ void k_loss(const float* __restrict__ z) {
    __shared__ float zr[ZD];
    __shared__ float sbuf[4];
    int i = blockIdx.x, t = threadIdx.x;
    int j = g_jp[i];
    zr[t] = z[(size_t)j * ZD + t];
    __syncthreads();
    float neg = NEG_INF;
    if (t < NP) {
        const float* pr = &g_prx[t * ZD];
        float dot = 0.f;
#pragma unroll 8
        for (int k = 0; k < ZD; k++) dot = fmaf(zr[k], pr[k], dot);
        float d2 = g_zz[j] + g_pss[t] - 2.f * dot
                 + 2.f * EPSV * (g_zs[j] - g_psum[t]) + EPS2T;
        neg = -sqrtf(fmaxf(d2, 0.f));
    }
    float m = block_max_128(neg, sbuf);
    float e = (t < NP) ? expf(neg - m) : 0.f;
    float s = block_sum_128(e, sbuf);
    if (t == 0) g_loss[i] = g_Dp[i] + (m + logf(s));
}

// ---------------- K7: deterministic mean -------------------------------------
// grid: 1 block x 1024 threads
__global__ void k_mean(float* __restrict__ out) {
    __shared__ float sv[1024];
    int t = threadIdx.x;
    float s = 0.f;
    for (int k = t; k < NA; k += 1024) s += g_loss[k];
    sv[t] = s;
    __syncthreads();
#pragma unroll
    for (int o = 512; o > 0; o >>= 1) {
        if (t < o) sv[t] += sv[t + o];
        __syncthreads();
    }
    if (t == 0) out[0] = sv[0] / (float)NA;
}

// ---------------- launch ------------------------------------------------------
extern "C" void kernel_launch(void* const* d_in, const int* in_sizes, int n_in,
                              void* d_out, int out_size) {
    const float* z       = (const float*)d_in[0];
    const int*   y_idx   = (const int*)d_in[1];
    const float* proxies = (const float*)d_in[2];
    const int*   y_map   = (const int*)d_in[3];
    float*       out     = (float*)d_out;

    k_prox<<<NP, 128>>>(proxies);
    k_zstats<<<64, 256>>>(z, y_idx, y_map);
    k_scan_scatter<<<1, 1024>>>();
    k_nearest<<<NA, 128>>>(z);
    k_hardpos<<<NA, 128>>>(z);
    k_loss<<<NA, 128>>>(z);
    k_mean<<<1, 1024>>>(out);
}

// round 2
// speedup vs baseline: 3.1637x; 3.1637x over previous
#include <cuda_runtime.h>
#include <cuda_bf16.h>
#include <math.h>

#define BN     8192      // samples
#define ZD     128       // feature dim
#define NC     62        // classes
#define NP     93        // proxies
#define P2     96        // padded proxy count (coalescing)
#define NA     2730      // anchors: 0,3,...,8187
#define AB     16        // anchors per block in batched kernels
#define NBLK   ((NA + AB - 1) / AB)   // 171
#define EPSV   1e-6f
#define EPS2T  1.28e-10f // ZD * EPS^2

// ---------------- persistent scratch (device globals; no allocs) -------------
__device__ float g_prx[NP * ZD];     // normalized proxies, row-major [p][k]
__device__ float g_prxT[ZD * P2];    // transposed + padded [k][p]
__device__ float g_pss[NP];          // sum(prx^2) per proxy row
__device__ float g_psum[NP];         // sum(prx) per proxy row
__device__ float g_zz[BN];           // sum(z^2) per sample
__device__ float g_zs[BN];           // sum(z)  per sample
__device__ int   g_yrel[BN];
__device__ int   g_cnt[NC];
__device__ int   g_cur[NC];
__device__ int   g_start[NC + 1];
__device__ int   g_clsidx[BN];
__device__ int   g_pidx[NA];
__device__ int   g_jp[NA];
__device__ float g_Dp[NA];
__device__ float g_loss[NA];

// ---------------- helpers ---------------------------------------------------
__device__ __forceinline__ float warp_sum(float v) {
#pragma unroll
    for (int o = 16; o; o >>= 1) v += __shfl_xor_sync(0xffffffffu, v, o);
    return v;
}

__device__ __forceinline__ float block_sum_128(float v, float* sbuf) {
    int lane = threadIdx.x & 31, w = threadIdx.x >> 5;
    v = warp_sum(v);
    if (lane == 0) sbuf[w] = v;
    __syncthreads();
    float r = sbuf[0] + sbuf[1] + sbuf[2] + sbuf[3];
    __syncthreads();
    return r;
}

// ---------------- K1: normalize proxies + transpose + zero counters ----------
// grid: NP blocks x 128 threads
__global__ void k_prox(const float* __restrict__ proxies) {
    __shared__ float sbuf[4];
    int b = blockIdx.x, t = threadIdx.x;
    if (b == 0 && t < NC) { g_cnt[t] = 0; g_cur[t] = 0; }
    if (b == 0) {   // zero transpose padding columns
        g_prxT[t * P2 + 93] = 0.f;
        g_prxT[t * P2 + 94] = 0.f;
        g_prxT[t * P2 + 95] = 0.f;
    }
    float v = proxies[b * ZD + t];
    float ss = block_sum_128(v * v, sbuf);
    float denom = fmaxf(sqrtf(ss), 1e-12f);
    float o = v / denom;
    g_prx[b * ZD + t] = o;
    g_prxT[t * P2 + b] = o;            // t = k index, b = proxy index
    float so  = block_sum_128(o, sbuf);
    float so2 = block_sum_128(o * o, sbuf);
    if (t == 0) { g_psum[b] = so; g_pss[b] = so2; }
}

// ---------------- K2: per-sample stats + y_rel + class histogram -------------
// grid: 64 blocks x 256 threads (512 warps, each warp handles 16 rows)
__global__ void k_zstats(const float* __restrict__ z,
                         const int* __restrict__ y_idx,
                         const int* __restrict__ y_map) {
    int gw = (blockIdx.x * blockDim.x + threadIdx.x) >> 5;
    int nw = (gridDim.x * blockDim.x) >> 5;
    int lane = threadIdx.x & 31;
    const float4* z4 = (const float4*)z;
    for (int row = gw; row < BN; row += nw) {
        float4 v = z4[(size_t)row * 32 + lane];
        float s  = (v.x + v.y) + (v.z + v.w);
        float ss = (v.x * v.x + v.y * v.y) + (v.z * v.z + v.w * v.w);
        s = warp_sum(s); ss = warp_sum(ss);
        if (lane == 0) {
            g_zs[row] = s; g_zz[row] = ss;
            int yi = y_idx[row];
            int r = 0;
            for (int k = 0; k < NC; k++) { if (y_map[k] == yi) { r = k; break; } }
            g_yrel[row] = r;
            atomicAdd(&g_cnt[r], 1);
        }
    }
}

// ---------------- K3: exclusive scan + scatter into class lists --------------
__global__ void k_scan_scatter() {
    __shared__ int sstart[NC + 1];
    if (threadIdx.x == 0) {
        int acc = 0;
        for (int c = 0; c < NC; c++) { sstart[c] = acc; acc += g_cnt[c]; }
        sstart[NC] = acc;
        for (int c = 0; c <= NC; c++) g_start[c] = sstart[c];
    }
    __syncthreads();
    for (int j = threadIdx.x; j < BN; j += blockDim.x) {
        int c = g_yrel[j];
        int pos = atomicAdd(&g_cur[c], 1);
        g_clsidx[sstart[c] + pos] = j;
    }
}

// ---------------- K4: nearest proxy, 16 anchors per block --------------------
// grid: NBLK blocks x 128 threads. Thread t (<96) owns proxy t; register-
// accumulates dots against 16 anchor rows staged in shared.
__global__ void __launch_bounds__(128) k_nearest(const float* __restrict__ z) {
    __shared__ float za[AB * ZD];   // 8 KB anchor tile
    __shared__ float sd[AB * P2];   // 6 KB distance tile
    int blk = blockIdx.x, t = threadIdx.x;
    int a0 = blk * AB;
    int na = NA - a0; if (na > AB) na = AB;

    for (int idx = t; idx < na * ZD; idx += 128) {
        int ai = idx >> 7, k = idx & 127;
        za[idx] = z[(size_t)(3 * (a0 + ai)) * ZD + k];
    }
    __syncthreads();

    if (t < P2) {
        float acc[AB];
#pragma unroll
        for (int a = 0; a < AB; a++) acc[a] = 0.f;
#pragma unroll 4
        for (int k = 0; k < ZD; k++) {
            float pv = g_prxT[k * P2 + t];
#pragma unroll
            for (int a = 0; a < AB; a++) acc[a] = fmaf(za[a * ZD + k], pv, acc[a]);
        }
        bool valid = (t < NP);
        float pss = valid ? g_pss[t]  : 0.f;
        float psm = valid ? g_psum[t] : 0.f;
#pragma unroll
        for (int a = 0; a < AB; a++) {
            float d = INFINITY;
            if (valid && a < na) {
                int s = 3 * (a0 + a);
                float d2 = g_zz[s] + pss - 2.f * acc[a]
                         + 2.f * EPSV * (g_zs[s] - psm) + EPS2T;
                d = sqrtf(fmaxf(d2, 0.f));
            }
            sd[a * P2 + t] = d;
        }
    }
    __syncthreads();

    int lane = t & 31, w = t >> 5;
    for (int a = w; a < na; a += 4) {
        float bv = INFINITY; int bi = 0x7fffffff;
#pragma unroll
        for (int q = 0; q < 3; q++) {
            int p = lane + 32 * q;
            float v = sd[a * P2 + p];
            if (v < bv || (v == bv && p < bi)) { bv = v; bi = p; }
        }
#pragma unroll
        for (int o = 16; o; o >>= 1) {
            float v2 = __shfl_xor_sync(0xffffffffu, bv, o);
            int   i2 = __shfl_xor_sync(0xffffffffu, bi, o);
            if (v2 < bv || (v2 == bv && i2 < bi)) { bv = v2; bi = i2; }
        }
        if (lane == 0) g_pidx[a0 + a] = bi;
    }
}

// ---------------- K5: hardest positive (sparse masked argmax, float4) --------
// grid: NA blocks x 128 threads; warp-cooperative dot, one LDG.128 per lane.
__global__ void __launch_bounds__(128) k_hardpos(const float* __restrict__ z) {
    int i = blockIdx.x, a = 3 * i, t = threadIdx.x;
    int lane = t & 31, w = t >> 5;
    __shared__ float4 s_pr[32];
    __shared__ float s_pss, s_psum;
    __shared__ float wv[4];
    __shared__ int   wj[4];
    int p = g_pidx[i];
    if (t < 32) s_pr[t] = ((const float4*)(g_prx + p * ZD))[t];
    if (t == 0) { s_pss = g_pss[p]; s_psum = g_psum[p]; }
    __syncthreads();
    float4 pr4 = s_pr[lane];
    int c = g_yrel[a];
    int s0 = g_start[c], s1 = g_start[c + 1];
    const float4* z4 = (const float4*)z;
    float bestv = -INFINITY; int bestj = 0x7fffffff;
    for (int idx = s0 + w; idx < s1; idx += 4) {
        int j = g_clsidx[idx];
        if (j < a) continue;           // suffix mask (warp-uniform)
        float4 v = z4[(size_t)j * 32 + lane];
        float dot = fmaf(pr4.x, v.x, fmaf(pr4.y, v.y, fmaf(pr4.z, v.z, pr4.w * v.w)));
        dot = warp_sum(dot);
        float d2 = s_pss + g_zz[j] - 2.f * dot
                 + 2.f * EPSV * (s_psum - g_zs[j]) + EPS2T;
        float d = sqrtf(fmaxf(d2, 0.f));
        if (d > bestv || (d == bestv && j < bestj)) { bestv = d; bestj = j; }
    }
    if (lane == 0) { wv[w] = bestv; wj[w] = bestj; }
    __syncthreads();
    if (t == 0) {
        float bv = wv[0]; int bj = wj[0];
#pragma unroll
        for (int q = 1; q < 4; q++)
            if (wv[q] > bv || (wv[q] == bv && wj[q] < bj)) { bv = wv[q]; bj = wj[q]; }
        g_jp[i] = bj; g_Dp[i] = bv;
    }
}

// ---------------- K6: D_n + logsumexp, 16 positives per block ----------------
__global__ void __launch_bounds__(128) k_loss(const float* __restrict__ z) {
    __shared__ float za[AB * ZD];
    __shared__ float sd[AB * P2];   // holds NEGATED distances
    __shared__ int   sj[AB];
    int blk = blockIdx.x, t = threadIdx.x;
    int a0 = blk * AB;
    int na = NA - a0; if (na > AB) na = AB;

    if (t < na) sj[t] = g_jp[a0 + t];
    __syncthreads();
    for (int idx = t; idx < na * ZD; idx += 128) {
        int ai = idx >> 7, k = idx & 127;
        za[idx] = z[(size_t)sj[ai] * ZD + k];
    }
    __syncthreads();

    if (t < P2) {
        float acc[AB];
#pragma unroll
        for (int a = 0; a < AB; a++) acc[a] = 0.f;
#pragma unroll 4
        for (int k = 0; k < ZD; k++) {
            float pv = g_prxT[k * P2 + t];
#pragma unroll
            for (int a = 0; a < AB; a++) acc[a] = fmaf(za[a * ZD + k], pv, acc[a]);
        }
        bool valid = (t < NP);
        float pss = valid ? g_pss[t]  : 0.f;
        float psm = valid ? g_psum[t] : 0.f;
#pragma unroll
        for (int a = 0; a < AB; a++) {
            float d = INFINITY;
            if (valid && a < na) {
                int j = sj[a];
                float d2 = g_zz[j] + pss - 2.f * acc[a]
                         + 2.f * EPSV * (g_zs[j] - psm) + EPS2T;
                d = sqrtf(fmaxf(d2, 0.f));
            }
            sd[a * P2 + t] = -d;
        }
    }
    __syncthreads();

    int lane = t & 31, w = t >> 5;
    for (int a = w; a < na; a += 4) {
        float m = -INFINITY;
#pragma unroll
        for (int q = 0; q < 3; q++) m = fmaxf(m, sd[a * P2 + lane + 32 * q]);
#pragma unroll
        for (int o = 16; o; o >>= 1) m = fmaxf(m, __shfl_xor_sync(0xffffffffu, m, o));
        float s = 0.f;
#pragma unroll
        for (int q = 0; q < 3; q++) s += expf(sd[a * P2 + lane + 32 * q] - m);
        s = warp_sum(s);
        if (lane == 0) g_loss[a0 + a] = g_Dp[a0 + a] + (m + logf(s));
    }
}

// ---------------- K7: deterministic mean -------------------------------------
__global__ void k_mean(float* __restrict__ out) {
    __shared__ float sv[1024];
    int t = threadIdx.x;
    float s = 0.f;
    for (int k = t; k < NA; k += 1024) s += g_loss[k];
    sv[t] = s;
    __syncthreads();
#pragma unroll
    for (int o = 512; o > 0; o >>= 1) {
        if (t < o) sv[t] += sv[t + o];
        __syncthreads();
    }
    if (t == 0) out[0] = sv[0] / (float)NA;
}

// ---------------- launch ------------------------------------------------------
extern "C" void kernel_launch(void* const* d_in, const int* in_sizes, int n_in,
                              void* d_out, int out_size) {
    const float* z       = (const float*)d_in[0];
    const int*   y_idx   = (const int*)d_in[1];
    const float* proxies = (const float*)d_in[2];
    const int*   y_map   = (const int*)d_in[3];
    float*       out     = (float*)d_out;

    k_prox<<<NP, 128>>>(proxies);
    k_zstats<<<64, 256>>>(z, y_idx, y_map);
    k_scan_scatter<<<1, 1024>>>();
    k_nearest<<<NBLK, 128>>>(z);
    k_hardpos<<<NA, 128>>>(z);
    k_loss<<<NBLK, 128>>>(z);
    k_mean<<<1, 1024>>>(out);
}

// round 3
// speedup vs baseline: 4.4352x; 1.4019x over previous
#include <cuda_runtime.h>
#include <cuda_bf16.h>
#include <math.h>

#define BN     8192      // samples
#define ZD     128       // feature dim
#define NC     62        // classes
#define NP     93        // proxies
#define P2     96        // padded proxy count
#define NA     2730      // anchors: 0,3,...,8187
#define AB     16        // anchors per tile block
#define NBLK4  171       // ceil(NA/AB)
#define EPSV   1e-6f
#define EPS2T  1.28e-10f // ZD * EPS^2

// ---------------- persistent scratch (device globals, zero-initialized) ------
__device__ float g_prx[NP * ZD];     // normalized proxies [p][k]
__device__ float g_prxT[ZD * P2];    // transposed [k][p], cols 93..95 stay 0
__device__ float g_pss[NP];
__device__ float g_psum[NP];
__device__ float g_zz[BN];
__device__ float g_zs[BN];
__device__ int   g_yrel[BN];
__device__ int   g_start[NC + 1];
__device__ int   g_clsidx[BN];
__device__ int   g_pidx[NA];
__device__ int   g_jp[NA];
__device__ float g_Dp[NA];
__device__ float g_loss[NA];
__device__ unsigned int g_done;      // last-block counter (self-resetting)

// ---------------- helpers ---------------------------------------------------
__device__ __forceinline__ float warp_sum(float v) {
#pragma unroll
    for (int o = 16; o; o >>= 1) v += __shfl_xor_sync(0xffffffffu, v, o);
    return v;
}

// ============ M1: proxy normalize (warp-per-proxy) + z stats =================
// grid: 12 + 128 = 140 blocks x 256 threads
__global__ void __launch_bounds__(256) k_pre(const float* __restrict__ z,
                                             const int* __restrict__ y_idx,
                                             const int* __restrict__ y_map,
                                             const float* __restrict__ proxies) {
    int b = blockIdx.x, t = threadIdx.x;
    int wid = t >> 5, lane = t & 31;
    if (b < 12) {                       // ---- proxy blocks: warp per proxy
        int p = b * 8 + wid;
        if (p < NP) {
            float4 v = ((const float4*)(proxies + p * ZD))[lane];
            float ss = warp_sum(v.x * v.x + v.y * v.y + v.z * v.z + v.w * v.w);
            float inv = 1.f / fmaxf(sqrtf(ss), 1e-12f);
            float4 o = make_float4(v.x * inv, v.y * inv, v.z * inv, v.w * inv);
            ((float4*)(g_prx + p * ZD))[lane] = o;
            int k0 = 4 * lane;
            g_prxT[(k0 + 0) * P2 + p] = o.x;
            g_prxT[(k0 + 1) * P2 + p] = o.y;
            g_prxT[(k0 + 2) * P2 + p] = o.z;
            g_prxT[(k0 + 3) * P2 + p] = o.w;
            float so  = warp_sum(o.x + o.y + o.z + o.w);
            float so2 = warp_sum(o.x * o.x + o.y * o.y + o.z * o.z + o.w * o.w);
            if (lane == 0) { g_psum[p] = so; g_pss[p] = so2; }
        }
    } else {                            // ---- zstats blocks: warp per 8 rows
        __shared__ int s_ymap[NC];
        if (t < NC) s_ymap[t] = y_map[t];
        __syncthreads();
        int wz = (b - 12) * 8 + wid;    // 0..1023
        const float4* z4 = (const float4*)z;
#pragma unroll
        for (int r = 0; r < 8; r++) {
            int row = wz * 8 + r;
            float4 v = z4[(size_t)row * 32 + lane];
            float s  = (v.x + v.y) + (v.z + v.w);
            float ss = (v.x * v.x + v.y * v.y) + (v.z * v.z + v.w * v.w);
#pragma unroll
            for (int o = 16; o; o >>= 1) {
                s  += __shfl_xor_sync(0xffffffffu, s, o);
                ss += __shfl_xor_sync(0xffffffffu, ss, o);
            }
            if (lane == 0) {
                g_zs[row] = s; g_zz[row] = ss;
                int yi = y_idx[row];
                int rr = 0;
                for (int k = 0; k < NC; k++) { if (s_ymap[k] == yi) { rr = k; break; } }
                g_yrel[row] = rr;
            }
        }
    }
}

// ============ M2: block 0 = scan+scatter, blocks 1..171 = nearest ============
// grid: 172 blocks x 128 threads
__global__ void __launch_bounds__(128) k_mid(const float* __restrict__ z) {
    int b = blockIdx.x, t = threadIdx.x;
    int lane = t & 31, w = t >> 5;

    if (b == 0) {   // ---------------- class histogram + scan + scatter -------
        __shared__ int cnt[NC];
        __shared__ int cur[NC];
        __shared__ int start[NC + 1];
        if (t < NC) cnt[t] = 0;
        __syncthreads();
        for (int j = t; j < BN; j += 128) atomicAdd(&cnt[g_yrel[j]], 1);
        __syncthreads();
        if (t == 0) {
            int acc = 0;
            for (int c = 0; c < NC; c++) { start[c] = acc; acc += cnt[c]; }
            start[NC] = acc;
        }
        __syncthreads();
        if (t < NC) { g_start[t] = start[t]; cur[t] = start[t]; }
        if (t == 0) g_start[NC] = start[NC];
        __syncthreads();
        for (int j = t; j < BN; j += 128) {
            int c = g_yrel[j];
            int pos = atomicAdd(&cur[c], 1);
            g_clsidx[pos] = j;
        }
        return;
    }

    // ---------------- nearest proxy: 16 anchors, 4x4 register tiles ---------
    __shared__ float s_za[AB * ZD];      // [a][k], 8 KB
    __shared__ float sd[AB * P2];        // 6 KB
    int blk = b - 1;
    int a0 = blk * AB;
    int na = NA - a0; if (na > AB) na = AB;

    const float4* z4 = (const float4*)z;
    for (int idx = t; idx < na * 32; idx += 128) {
        int ai = idx >> 5, k4 = idx & 31;
        ((float4*)s_za)[ai * 32 + k4] = z4[(size_t)(3 * (a0 + ai)) * 32 + k4];
    }
    __syncthreads();

    if (t < 96) {
        int pg = t % 24, ag = t / 24;        // proxy group (4), anchor group (4)
        int p0 = 4 * pg, al = 4 * ag;
        const float4* prxT4 = (const float4*)g_prxT;
        float acc[4][4];
#pragma unroll
        for (int i = 0; i < 4; i++)
#pragma unroll
            for (int j = 0; j < 4; j++) acc[i][j] = 0.f;
#pragma unroll 8
        for (int k = 0; k < ZD; k++) {
            float4 pv = prxT4[k * 24 + pg];
#pragma unroll
            for (int i = 0; i < 4; i++) {
                float zv = s_za[(al + i) * ZD + k];
                acc[i][0] = fmaf(zv, pv.x, acc[i][0]);
                acc[i][1] = fmaf(zv, pv.y, acc[i][1]);
                acc[i][2] = fmaf(zv, pv.z, acc[i][2]);
                acc[i][3] = fmaf(zv, pv.w, acc[i][3]);
            }
        }
        float pss[4], psm[4];
#pragma unroll
        for (int j = 0; j < 4; j++) {
            bool vp = (p0 + j) < NP;
            pss[j] = vp ? g_pss[p0 + j]  : 0.f;
            psm[j] = vp ? g_psum[p0 + j] : 0.f;
        }
#pragma unroll
        for (int i = 0; i < 4; i++) {
            if (al + i < na) {
                int s = 3 * (a0 + al + i);
                float zzv = g_zz[s], zsv = g_zs[s];
#pragma unroll
                for (int j = 0; j < 4; j++) {
                    float d = INFINITY;
                    if (p0 + j < NP) {
                        float d2 = zzv + pss[j] - 2.f * acc[i][j]
                                 + 2.f * EPSV * (zsv - psm[j]) + EPS2T;
                        d = sqrtf(fmaxf(d2, 0.f));
                    }
                    sd[(al + i) * P2 + p0 + j] = d;
                }
            }
        }
    }
    __syncthreads();

    for (int a = w; a < na; a += 4) {
        float bv = INFINITY; int bi = 0x7fffffff;
#pragma unroll
        for (int q = 0; q < 3; q++) {
            int p = lane + 32 * q;
            float v = sd[a * P2 + p];
            if (v < bv || (v == bv && p < bi)) { bv = v; bi = p; }
        }
#pragma unroll
        for (int o = 16; o; o >>= 1) {
            float v2 = __shfl_xor_sync(0xffffffffu, bv, o);
            int   i2 = __shfl_xor_sync(0xffffffffu, bi, o);
            if (v2 < bv || (v2 == bv && i2 < bi)) { bv = v2; bi = i2; }
        }
        if (lane == 0) g_pidx[a0 + a] = bi;
    }
}

// ============ K5: hardest positive with candidate compaction =================
// grid: NA blocks x 128 threads
__global__ void __launch_bounds__(128) k_hardpos(const float* __restrict__ z) {
    int i = blockIdx.x, a = 3 * i, t = threadIdx.x;
    int lane = t & 31, w = t >> 5;
    __shared__ float4 s_pr[32];
    __shared__ float s_pss, s_psum;
    __shared__ int s_cand[512];
    __shared__ int s_n;
    __shared__ float wv[4];
    __shared__ int   wj[4];

    int p = g_pidx[i];
    if (t < 32) s_pr[t] = ((const float4*)(g_prx + p * ZD))[t];
    if (t == 0) { s_pss = g_pss[p]; s_psum = g_psum[p]; s_n = 0; }
    int c = g_yrel[a];
    int s0 = g_start[c], s1 = g_start[c + 1];
    __syncthreads();

    for (int idx = s0 + t; idx < s1; idx += 128) {
        int j = g_clsidx[idx];
        if (j >= a) { int pos = atomicAdd(&s_n, 1); s_cand[pos] = j; }
    }
    __syncthreads();
    int n = s_n;

    float4 pr4 = s_pr[lane];
    const float4* z4 = (const float4*)z;
    float bestv = -INFINITY; int bestj = 0x7fffffff;
    for (int q = w; q < n; q += 4) {
        int j = s_cand[q];
        float4 v = z4[(size_t)j * 32 + lane];
        float dot = fmaf(pr4.x, v.x, fmaf(pr4.y, v.y, fmaf(pr4.z, v.z, pr4.w * v.w)));
        dot = warp_sum(dot);
        float d2 = s_pss + g_zz[j] - 2.f * dot
                 + 2.f * EPSV * (s_psum - g_zs[j]) + EPS2T;
        float d = sqrtf(fmaxf(d2, 0.f));
        if (d > bestv || (d == bestv && j < bestj)) { bestv = d; bestj = j; }
    }
    if (lane == 0) { wv[w] = bestv; wj[w] = bestj; }
    __syncthreads();
    if (t == 0) {
        float bv = wv[0]; int bj = wj[0];
#pragma unroll
        for (int q = 1; q < 4; q++)
            if (wv[q] > bv || (wv[q] == bv && wj[q] < bj)) { bv = wv[q]; bj = wj[q]; }
        g_jp[i] = bj; g_Dp[i] = bv;
    }
}

// ============ M3: logsumexp loss tiles + last-block mean =====================
// grid: NBLK4 blocks x 128 threads
__global__ void __launch_bounds__(128) k_post(const float* __restrict__ z,
                                              float* __restrict__ out) {
    __shared__ float s_za[AB * ZD];
    __shared__ float sd[AB * P2];    // negated distances
    __shared__ int   sj[AB];
    __shared__ int   amLast;
    __shared__ float rbuf[4];
    int blk = blockIdx.x, t = threadIdx.x;
    int lane = t & 31, w = t >> 5;
    int a0 = blk * AB;
    int na = NA - a0; if (na > AB) na = AB;

    if (t < na) sj[t] = g_jp[a0 + t];
    __syncthreads();
    const float4* z4 = (const float4*)z;
    for (int idx = t; idx < na * 32; idx += 128) {
        int ai = idx >> 5, k4 = idx & 31;
        ((float4*)s_za)[ai * 32 + k4] = z4[(size_t)sj[ai] * 32 + k4];
    }
    __syncthreads();

    if (t < 96) {
        int pg = t % 24, ag = t / 24;
        int p0 = 4 * pg, al = 4 * ag;
        const float4* prxT4 = (const float4*)g_prxT;
        float acc[4][4];
#pragma unroll
        for (int i = 0; i < 4; i++)
#pragma unroll
            for (int j = 0; j < 4; j++) acc[i][j] = 0.f;
#pragma unroll 8
        for (int k = 0; k < ZD; k++) {
            float4 pv = prxT4[k * 24 + pg];
#pragma unroll
            for (int i = 0; i < 4; i++) {
                float zv = s_za[(al + i) * ZD + k];
                acc[i][0] = fmaf(zv, pv.x, acc[i][0]);
                acc[i][1] = fmaf(zv, pv.y, acc[i][1]);
                acc[i][2] = fmaf(zv, pv.z, acc[i][2]);
                acc[i][3] = fmaf(zv, pv.w, acc[i][3]);
            }
        }
        float pss[4], psm[4];
#pragma unroll
        for (int j = 0; j < 4; j++) {
            bool vp = (p0 + j) < NP;
            pss[j] = vp ? g_pss[p0 + j]  : 0.f;
            psm[j] = vp ? g_psum[p0 + j] : 0.f;
        }
#pragma unroll
        for (int i = 0; i < 4; i++) {
            if (al + i < na) {
                int jrow = sj[al + i];
                float zzv = g_zz[jrow], zsv = g_zs[jrow];
#pragma unroll
                for (int j = 0; j < 4; j++) {
                    float nd = -INFINITY;
                    if (p0 + j < NP) {
                        float d2 = zzv + pss[j] - 2.f * acc[i][j]
                                 + 2.f * EPSV * (zsv - psm[j]) + EPS2T;
                        nd = -sqrtf(fmaxf(d2, 0.f));
                    }
                    sd[(al + i) * P2 + p0 + j] = nd;
                }
            }
        }
    }
    __syncthreads();

    for (int a = w; a < na; a += 4) {
        float m = -INFINITY;
#pragma unroll
        for (int q = 0; q < 3; q++) m = fmaxf(m, sd[a * P2 + lane + 32 * q]);
#pragma unroll
        for (int o = 16; o; o >>= 1) m = fmaxf(m, __shfl_xor_sync(0xffffffffu, m, o));
        float s = 0.f;
#pragma unroll
        for (int q = 0; q < 3; q++) s += expf(sd[a * P2 + lane + 32 * q] - m);
        s = warp_sum(s);
        if (lane == 0) g_loss[a0 + a] = g_Dp[a0 + a] + (m + logf(s));
    }

    // ---- last block computes the mean ----
    __threadfence();
    __syncthreads();
    if (t == 0) {
        unsigned int old = atomicAdd(&g_done, 1u);
        amLast = (old == (unsigned)(gridDim.x - 1));
    }
    __syncthreads();
    if (amLast) {
        __threadfence();
        float s = 0.f;
        for (int k = t; k < NA; k += 128) s += g_loss[k];
        s = warp_sum(s);
        if (lane == 0) rbuf[w] = s;
        __syncthreads();
        if (t == 0) {
            float total = rbuf[0] + rbuf[1] + rbuf[2] + rbuf[3];
            out[0] = total / (float)NA;
            g_done = 0;                 // self-reset for next replay
        }
    }
}

// ---------------- launch ------------------------------------------------------
extern "C" void kernel_launch(void* const* d_in, const int* in_sizes, int n_in,
                              void* d_out, int out_size) {
    const float* z       = (const float*)d_in[0];
    const int*   y_idx   = (const int*)d_in[1];
    const float* proxies = (const float*)d_in[2];
    const int*   y_map   = (const int*)d_in[3];
    float*       out     = (float*)d_out;

    k_pre<<<140, 256>>>(z, y_idx, y_map, proxies);
    k_mid<<<NBLK4 + 1, 128>>>(z);
    k_hardpos<<<NA, 128>>>(z);
    k_post<<<NBLK4, 128>>>(z, out);
}

// round 4
// speedup vs baseline: 7.8912x; 1.7792x over previous
#include <cuda_runtime.h>
#include <cuda_bf16.h>
#include <math.h>

#define BN     8192
#define ZD     128
#define NC     62
#define NP     93
#define P2     96        // padded proxies
#define NA     2730      // anchors 0,3,...,8187
#define EPSV   1e-6f
#define EPS2T  1.28e-10f // ZD*EPS^2
#define SZP    132       // padded smem z row (floats)
#define HB_W   8         // anchors (warps) per k_hard block
#define HGRID  ((NA + HB_W - 1) / HB_W)   // 342

// ---------------- persistent scratch (device globals, zero-init) -------------
__device__ float g_prxT[ZD * P2];      // [k][p], cols 93..95 remain 0
__device__ float g_pss[P2];            // pad entries remain 0
__device__ float g_psum[P2];
__device__ float g_zz[BN];
__device__ float g_zs[BN];
__device__ int   g_yrel[BN];
__device__ int   g_start[NC + 1];
__device__ int   g_clsidx[BN];
__device__ float g_Dpz[P2 * BN];       // dist(proxy p, z j), eps sign psum-zs
__device__ float g_DT [BN * P2];       // dist(z j, proxy p), eps sign zs-psum
__device__ float g_loss[NA];
__device__ unsigned int g_done;

// ---------------- helpers ---------------------------------------------------
__device__ __forceinline__ float warp_sum(float v) {
#pragma unroll
    for (int o = 16; o; o >>= 1) v += __shfl_xor_sync(0xffffffffu, v, o);
    return v;
}
// all lanes end with the winning (v,i); min variant
__device__ __forceinline__ void warp_argmin(float& v, int& i) {
#pragma unroll
    for (int o = 16; o; o >>= 1) {
        float v2 = __shfl_xor_sync(0xffffffffu, v, o);
        int   i2 = __shfl_xor_sync(0xffffffffu, i, o);
        if (v2 < v || (v2 == v && i2 < i)) { v = v2; i = i2; }
    }
}
__device__ __forceinline__ void warp_argmax(float& v, int& i) {
#pragma unroll
    for (int o = 16; o; o >>= 1) {
        float v2 = __shfl_xor_sync(0xffffffffu, v, o);
        int   i2 = __shfl_xor_sync(0xffffffffu, i, o);
        if (v2 > v || (v2 == v && i2 < i)) { v = v2; i = i2; }
    }
}

// ============ K1: proxy normalize + transpose + z stats + yrel ===============
// grid: 140 blocks x 256 threads (blocks 0..11 proxies, 12..139 z rows)
__global__ void __launch_bounds__(256) k_pre(const float* __restrict__ z,
                                             const int* __restrict__ y_idx,
                                             const int* __restrict__ y_map,
                                             const float* __restrict__ proxies) {
    int b = blockIdx.x, t = threadIdx.x;
    int wid = t >> 5, lane = t & 31;
    if (b < 12) {                        // warp per proxy
        int p = b * 8 + wid;
        if (p < NP) {
            float4 v = ((const float4*)(proxies + p * ZD))[lane];
            float ss = warp_sum(v.x * v.x + v.y * v.y + v.z * v.z + v.w * v.w);
            float inv = 1.f / fmaxf(sqrtf(ss), 1e-12f);
            float4 o = make_float4(v.x * inv, v.y * inv, v.z * inv, v.w * inv);
            int k0 = 4 * lane;
            g_prxT[(k0 + 0) * P2 + p] = o.x;
            g_prxT[(k0 + 1) * P2 + p] = o.y;
            g_prxT[(k0 + 2) * P2 + p] = o.z;
            g_prxT[(k0 + 3) * P2 + p] = o.w;
            float so  = warp_sum(o.x + o.y + o.z + o.w);
            float so2 = warp_sum(o.x * o.x + o.y * o.y + o.z * o.z + o.w * o.w);
            if (lane == 0) { g_psum[p] = so; g_pss[p] = so2; }
        }
    } else {                             // warp per 8 z rows
        __shared__ int s_ymap[NC];
        if (t < NC) s_ymap[t] = y_map[t];
        __syncthreads();
        int wz = (b - 12) * 8 + wid;     // 0..1023
        const float4* z4 = (const float4*)z;
#pragma unroll
        for (int r = 0; r < 8; r++) {
            int row = wz * 8 + r;
            float4 v = z4[(size_t)row * 32 + lane];
            float s  = (v.x + v.y) + (v.z + v.w);
            float ss = (v.x * v.x + v.y * v.y) + (v.z * v.z + v.w * v.w);
#pragma unroll
            for (int o = 16; o; o >>= 1) {
                s  += __shfl_xor_sync(0xffffffffu, s, o);
                ss += __shfl_xor_sync(0xffffffffu, ss, o);
            }
            if (lane == 0) {
                g_zs[row] = s; g_zz[row] = ss;
                int yi = y_idx[row];
                int rr = 0;
                for (int k = 0; k < NC; k++) { if (s_ymap[k] == yi) { rr = k; break; } }
                g_yrel[row] = rr;
            }
        }
    }
}

// ============ K2: dense distance matrix (both eps variants) + scatter ========
// grid: 129 blocks x 384 threads. Blocks 0..127: 96x64 tile. Block 128: scatter.
__global__ void __launch_bounds__(384) k_dist(const float* __restrict__ z) {
    int b = blockIdx.x, t = threadIdx.x;
    __shared__ float s_z[64 * SZP];      // ~33.8 KB, padded rows

    if (b == 128) {  // ---- class histogram + scan + scatter ----
        __shared__ int cnt[NC], cur[NC], start[NC + 1];
        if (t < NC) cnt[t] = 0;
        __syncthreads();
        for (int j = t; j < BN; j += 384) atomicAdd(&cnt[g_yrel[j]], 1);
        __syncthreads();
        if (t == 0) {
            int acc = 0;
            for (int c = 0; c < NC; c++) { start[c] = acc; acc += cnt[c]; }
            start[NC] = acc;
        }
        __syncthreads();
        if (t < NC) { g_start[t] = start[t]; cur[t] = start[t]; }
        if (t == 0) g_start[NC] = start[NC];
        __syncthreads();
        for (int j = t; j < BN; j += 384) {
            int c = g_yrel[j];
            int pos = atomicAdd(&cur[c], 1);
            g_clsidx[pos] = j;
        }
        return;
    }

    // ---- stage 64 z rows into padded shared ----
    const float4* z4 = (const float4*)z;
    for (int idx = t; idx < 64 * 32; idx += 384) {
        int r = idx >> 5, q = idx & 31;
        float4 v = z4[(size_t)(b * 64 + r) * 32 + q];
        float* dst = &s_z[r * SZP + 4 * q];
        dst[0] = v.x; dst[1] = v.y; dst[2] = v.z; dst[3] = v.w;
    }
    __syncthreads();

    int pg = t % 24, sg = t / 24;        // 24 proxy-groups x 16 sample-groups
    int p0 = 4 * pg, s0 = 4 * sg;
    const float4* prxT4 = (const float4*)g_prxT;   // [k][24 x float4]

    float acc[4][4];                      // [proxy j][sample i]
#pragma unroll
    for (int j = 0; j < 4; j++)
#pragma unroll
        for (int i = 0; i < 4; i++) acc[j][i] = 0.f;

#pragma unroll 4
    for (int k = 0; k < ZD; k++) {
        float4 pv = prxT4[k * 24 + pg];   // L1-resident 48 KB
        float zv0 = s_z[(s0 + 0) * SZP + k];
        float zv1 = s_z[(s0 + 1) * SZP + k];
        float zv2 = s_z[(s0 + 2) * SZP + k];
        float zv3 = s_z[(s0 + 3) * SZP + k];
        acc[0][0] = fmaf(pv.x, zv0, acc[0][0]); acc[0][1] = fmaf(pv.x, zv1, acc[0][1]);
        acc[0][2] = fmaf(pv.x, zv2, acc[0][2]); acc[0][3] = fmaf(pv.x, zv3, acc[0][3]);
        acc[1][0] = fmaf(pv.y, zv0, acc[1][0]); acc[1][1] = fmaf(pv.y, zv1, acc[1][1]);
        acc[1][2] = fmaf(pv.y, zv2, acc[1][2]); acc[1][3] = fmaf(pv.y, zv3, acc[1][3]);
        acc[2][0] = fmaf(pv.z, zv0, acc[2][0]); acc[2][1] = fmaf(pv.z, zv1, acc[2][1]);
        acc[2][2] = fmaf(pv.z, zv2, acc[2][2]); acc[2][3] = fmaf(pv.z, zv3, acc[2][3]);
        acc[3][0] = fmaf(pv.w, zv0, acc[3][0]); acc[3][1] = fmaf(pv.w, zv1, acc[3][1]);
        acc[3][2] = fmaf(pv.w, zv2, acc[3][2]); acc[3][3] = fmaf(pv.w, zv3, acc[3][3]);
    }

    int sBase = b * 64 + s0;
    float pssv[4], psmv[4], zzv[4], zsv[4];
#pragma unroll
    for (int j = 0; j < 4; j++) { pssv[j] = g_pss[p0 + j]; psmv[j] = g_psum[p0 + j]; }
#pragma unroll
    for (int i = 0; i < 4; i++) { zzv[i] = g_zz[sBase + i]; zsv[i] = g_zs[sBase + i]; }

    float dpz[4][4], dzp[4][4];
#pragma unroll
    for (int j = 0; j < 4; j++)
#pragma unroll
        for (int i = 0; i < 4; i++) {
            float base = zzv[i] + pssv[j] - 2.f * acc[j][i];
            float e = 2.f * EPSV * (psmv[j] - zsv[i]);
            dpz[j][i] = sqrtf(fmaxf(base + e + EPS2T, 0.f));
            dzp[j][i] = sqrtf(fmaxf(base - e + EPS2T, 0.f));
        }

#pragma unroll
    for (int j = 0; j < 4; j++)   // D_pz rows: float4 over samples
        *(float4*)(g_Dpz + (size_t)(p0 + j) * BN + sBase) =
            make_float4(dpz[j][0], dpz[j][1], dpz[j][2], dpz[j][3]);
#pragma unroll
    for (int i = 0; i < 4; i++)   // DT rows: float4 over proxies
        *(float4*)(g_DT + (size_t)(sBase + i) * P2 + p0) =
            make_float4(dzp[0][i], dzp[1][i], dzp[2][i], dzp[3][i]);
}

// ============ K3: warp-per-anchor: nearest + hardpos + lse + mean ============
// grid: HGRID blocks x 256 threads
__global__ void __launch_bounds__(256) k_hard(float* __restrict__ out) {
    __shared__ float rbuf[8];
    __shared__ int s_last;
    int t = threadIdx.x, w = t >> 5, lane = t & 31;
    int i = blockIdx.x * HB_W + w;

    if (i < NA) {
        int a = 3 * i;
        // ---- nearest proxy: argmin over DT[a][*] ----
        float bv = INFINITY; int bp = 0x7fffffff;
        const float* dta = g_DT + (size_t)a * P2;
#pragma unroll
        for (int q = 0; q < 3; q++) {
            int p = lane + 32 * q;
            float d = (p < NP) ? dta[p] : INFINITY;
            if (d < bv || (d == bv && p < bp)) { bv = d; bp = p; }
        }
        warp_argmin(bv, bp);
        int px = bp;

        // ---- hardest positive: argmax over masked class suffix ----
        int c = g_yrel[a];
        int lo = g_start[c], hi = g_start[c + 1];
        const float* Drow = g_Dpz + (size_t)px * BN;
        float hb = -INFINITY; int hj = 0x7fffffff;
        for (int idx = lo + lane; idx < hi; idx += 32) {
            int j = g_clsidx[idx];
            if (j >= a) {
                float d = Drow[j];
                if (d > hb || (d == hb && j < hj)) { hb = d; hj = j; }
            }
        }
        warp_argmax(hb, hj);          // hj = j_p, hb = D_p (all lanes)

        // ---- logsumexp over -DT[j_p][*] ----
        const float* dtj = g_DT + (size_t)hj * P2;
        float nd0 = (lane      < NP) ? -dtj[lane]      : -INFINITY;
        float nd1 = (lane + 32 < NP) ? -dtj[lane + 32] : -INFINITY;
        float nd2 = (lane + 64 < NP) ? -dtj[lane + 64] : -INFINITY;
        float m = fmaxf(nd0, fmaxf(nd1, nd2));
#pragma unroll
        for (int o = 16; o; o >>= 1) m = fmaxf(m, __shfl_xor_sync(0xffffffffu, m, o));
        float s = expf(nd0 - m) + expf(nd1 - m) + expf(nd2 - m);
        s = warp_sum(s);
        if (lane == 0) g_loss[i] = hb + (m + logf(s));
    }

    // ---- last block computes deterministic mean ----
    __threadfence();
    __syncthreads();
    if (t == 0) s_last = (atomicAdd(&g_done, 1u) == (unsigned)(gridDim.x - 1));
    __syncthreads();
    if (s_last) {
        __threadfence();
        float s = 0.f;
        for (int k = t; k < NA; k += 256) s += g_loss[k];
        s = warp_sum(s);
        if (lane == 0) rbuf[w] = s;
        __syncthreads();
        if (t == 0) {
            float total = 0.f;
#pragma unroll
            for (int q = 0; q < 8; q++) total += rbuf[q];
            out[0] = total / (float)NA;
            g_done = 0;
        }
    }
}

// ---------------- launch ------------------------------------------------------
extern "C" void kernel_launch(void* const* d_in, const int* in_sizes, int n_in,
                              void* d_out, int out_size) {
    const float* z       = (const float*)d_in[0];
    const int*   y_idx   = (const int*)d_in[1];
    const float* proxies = (const float*)d_in[2];
    const int*   y_map   = (const int*)d_in[3];
    float*       out     = (float*)d_out;

    k_pre<<<140, 256>>>(z, y_idx, y_map, proxies);
    k_dist<<<129, 384>>>(z);
    k_hard<<<HGRID, 256>>>(out);
}

// round 5
// speedup vs baseline: 8.7507x; 1.1089x over previous
#include <cuda_runtime.h>
#include <cuda_bf16.h>
#include <math.h>

#define BN     8192
#define ZD     128
#define NC     62
#define NP     93
#define P2     96        // padded proxies
#define NA     2730      // anchors 0,3,...,8187
#define EPSV   1e-6f
#define EPS2T  1.28e-10f // ZD*EPS^2
#define SZP    132       // padded smem z row (floats)
#define HB_W   8         // anchors (warps) per k_hard block
#define HGRID  ((NA + HB_W - 1) / HB_W)   // 342

// ---------------- persistent scratch (device globals, zero-init) -------------
__device__ float g_prxT[ZD * P2];      // [k][p], cols 93..95 remain 0
__device__ float g_pss[P2];            // pad entries remain 0
__device__ float g_psum[P2];
__device__ int   g_yrel[BN];
__device__ int   g_start[NC + 1];
__device__ int   g_clsidx[BN];
__device__ float g_Dpz[P2 * BN];       // dist(proxy p, z j), eps sign psum-zs
__device__ float g_DT [BN * P2];       // dist(z j, proxy p), eps sign zs-psum
__device__ float g_loss[NA];
__device__ unsigned int g_done;

// ---------------- helpers ---------------------------------------------------
__device__ __forceinline__ float warp_sum(float v) {
#pragma unroll
    for (int o = 16; o; o >>= 1) v += __shfl_xor_sync(0xffffffffu, v, o);
    return v;
}
__device__ __forceinline__ void warp_argmin(float& v, int& i) {
#pragma unroll
    for (int o = 16; o; o >>= 1) {
        float v2 = __shfl_xor_sync(0xffffffffu, v, o);
        int   i2 = __shfl_xor_sync(0xffffffffu, i, o);
        if (v2 < v || (v2 == v && i2 < i)) { v = v2; i = i2; }
    }
}
__device__ __forceinline__ void warp_argmax(float& v, int& i) {
#pragma unroll
    for (int o = 16; o; o >>= 1) {
        float v2 = __shfl_xor_sync(0xffffffffu, v, o);
        int   i2 = __shfl_xor_sync(0xffffffffu, i, o);
        if (v2 > v || (v2 == v && i2 < i)) { v = v2; i = i2; }
    }
}

// ============ K1: proxy normalize + transpose, y_rel via inverse map =========
// grid: 20 blocks x 256 threads (0..11 proxies, 12..19 y_rel). No z reads.
__global__ void __launch_bounds__(256) k_pre(const int* __restrict__ y_idx,
                                             const int* __restrict__ y_map,
                                             const float* __restrict__ proxies) {
    int b = blockIdx.x, t = threadIdx.x;
    int wid = t >> 5, lane = t & 31;
    if (b < 12) {                        // warp per proxy
        int p = b * 8 + wid;
        if (p < NP) {
            float4 v = ((const float4*)(proxies + p * ZD))[lane];
            float ss = warp_sum(v.x * v.x + v.y * v.y + v.z * v.z + v.w * v.w);
            float inv = 1.f / fmaxf(sqrtf(ss), 1e-12f);
            float4 o = make_float4(v.x * inv, v.y * inv, v.z * inv, v.w * inv);
            int k0 = 4 * lane;
            g_prxT[(k0 + 0) * P2 + p] = o.x;
            g_prxT[(k0 + 1) * P2 + p] = o.y;
            g_prxT[(k0 + 2) * P2 + p] = o.z;
            g_prxT[(k0 + 3) * P2 + p] = o.w;
            float so  = warp_sum(o.x + o.y + o.z + o.w);
            float so2 = warp_sum(o.x * o.x + o.y * o.y + o.z * o.z + o.w * o.w);
            if (lane == 0) { g_psum[p] = so; g_pss[p] = so2; }
        }
    } else {                             // y_rel: inverse-map lookup
        __shared__ int s_inv[NC];
        if (t < NC) s_inv[y_map[t]] = t; // y_map values are a permutation of 0..61
        __syncthreads();
        int base = (b - 12) * 1024;
#pragma unroll
        for (int r = 0; r < 4; r++) {
            int row = base + r * 256 + t;
            g_yrel[row] = s_inv[y_idx[row]];
        }
    }
}

// ============ K2: dense distance matrix + in-tile z stats + scatter ==========
// grid: 129 blocks x 384 threads. Blocks 0..127: 96x64 tile. Block 128: scatter.
__global__ void __launch_bounds__(384) k_dist(const float* __restrict__ z) {
    int b = blockIdx.x, t = threadIdx.x;
    int lane = t & 31;
    __shared__ float s_z[64 * SZP];      // ~33.8 KB
    __shared__ float s_zz[64], s_zs[64];

    if (b == 128) {  // ---- class histogram + scan + scatter ----
        __shared__ int cnt[NC], cur[NC], start[NC + 1];
        if (t < NC) cnt[t] = 0;
        __syncthreads();
        for (int j = t; j < BN; j += 384) atomicAdd(&cnt[g_yrel[j]], 1);
        __syncthreads();
        if (t == 0) {
            int acc = 0;
            for (int c = 0; c < NC; c++) { start[c] = acc; acc += cnt[c]; }
            start[NC] = acc;
        }
        __syncthreads();
        if (t < NC) { g_start[t] = start[t]; cur[t] = start[t]; }
        if (t == 0) g_start[NC] = start[NC];
        __syncthreads();
        for (int j = t; j < BN; j += 384) {
            int c = g_yrel[j];
            int pos = atomicAdd(&cur[c], 1);
            g_clsidx[pos] = j;
        }
        return;
    }

    // ---- stage 64 z rows; stride 384 is warp-aligned so each warp-iter
    //      covers one full row with lanes = column quads -> free row stats ----
    const float4* z4 = (const float4*)z;
    for (int idx = t; idx < 64 * 32; idx += 384) {
        int r = idx >> 5, q = idx & 31;          // r is warp-uniform
        float4 v = z4[(size_t)(b * 64 + r) * 32 + q];
        float* dst = &s_z[r * SZP + 4 * q];
        dst[0] = v.x; dst[1] = v.y; dst[2] = v.z; dst[3] = v.w;
        float s  = (v.x + v.y) + (v.z + v.w);
        float ss = (v.x * v.x + v.y * v.y) + (v.z * v.z + v.w * v.w);
#pragma unroll
        for (int o = 16; o; o >>= 1) {
            s  += __shfl_xor_sync(0xffffffffu, s, o);
            ss += __shfl_xor_sync(0xffffffffu, ss, o);
        }
        if (lane == 0) { s_zs[r] = s; s_zz[r] = ss; }
    }
    __syncthreads();

    int pg = t % 24, sg = t / 24;        // 24 proxy-groups x 16 sample-groups
    int p0 = 4 * pg, s0 = 4 * sg;
    const float4* prxT4 = (const float4*)g_prxT;

    float acc[4][4];                      // [proxy j][sample i]
#pragma unroll
    for (int j = 0; j < 4; j++)
#pragma unroll
        for (int i = 0; i < 4; i++) acc[j][i] = 0.f;

#pragma unroll 4
    for (int k = 0; k < ZD; k++) {
        float4 pv = prxT4[k * 24 + pg];   // 48 KB, L1-resident
        float zv0 = s_z[(s0 + 0) * SZP + k];
        float zv1 = s_z[(s0 + 1) * SZP + k];
        float zv2 = s_z[(s0 + 2) * SZP + k];
        float zv3 = s_z[(s0 + 3) * SZP + k];
        acc[0][0] = fmaf(pv.x, zv0, acc[0][0]); acc[0][1] = fmaf(pv.x, zv1, acc[0][1]);
        acc[0][2] = fmaf(pv.x, zv2, acc[0][2]); acc[0][3] = fmaf(pv.x, zv3, acc[0][3]);
        acc[1][0] = fmaf(pv.y, zv0, acc[1][0]); acc[1][1] = fmaf(pv.y, zv1, acc[1][1]);
        acc[1][2] = fmaf(pv.y, zv2, acc[1][2]); acc[1][3] = fmaf(pv.y, zv3, acc[1][3]);
        acc[2][0] = fmaf(pv.z, zv0, acc[2][0]); acc[2][1] = fmaf(pv.z, zv1, acc[2][1]);
        acc[2][2] = fmaf(pv.z, zv2, acc[2][2]); acc[2][3] = fmaf(pv.z, zv3, acc[2][3]);
        acc[3][0] = fmaf(pv.w, zv0, acc[3][0]); acc[3][1] = fmaf(pv.w, zv1, acc[3][1]);
        acc[3][2] = fmaf(pv.w, zv2, acc[3][2]); acc[3][3] = fmaf(pv.w, zv3, acc[3][3]);
    }

    int sBase = b * 64 + s0;
    float pssv[4], psmv[4], zzv[4], zsv[4];
#pragma unroll
    for (int j = 0; j < 4; j++) { pssv[j] = g_pss[p0 + j]; psmv[j] = g_psum[p0 + j]; }
#pragma unroll
    for (int i = 0; i < 4; i++) { zzv[i] = s_zz[s0 + i]; zsv[i] = s_zs[s0 + i]; }

    float dpz[4][4], dzp[4][4];
#pragma unroll
    for (int j = 0; j < 4; j++)
#pragma unroll
        for (int i = 0; i < 4; i++) {
            float base = zzv[i] + pssv[j] - 2.f * acc[j][i];
            float e = 2.f * EPSV * (psmv[j] - zsv[i]);
            dpz[j][i] = sqrtf(fmaxf(base + e + EPS2T, 0.f));
            dzp[j][i] = sqrtf(fmaxf(base - e + EPS2T, 0.f));
        }

#pragma unroll
    for (int j = 0; j < 4; j++)
        *(float4*)(g_Dpz + (size_t)(p0 + j) * BN + sBase) =
            make_float4(dpz[j][0], dpz[j][1], dpz[j][2], dpz[j][3]);
#pragma unroll
    for (int i = 0; i < 4; i++)
        *(float4*)(g_DT + (size_t)(sBase + i) * P2 + p0) =
            make_float4(dzp[0][i], dzp[1][i], dzp[2][i], dzp[3][i]);
}

// ============ K3: warp-per-anchor: nearest + hardpos + lse + mean ============
// grid: HGRID blocks x 256 threads
__global__ void __launch_bounds__(256) k_hard(float* __restrict__ out) {
    __shared__ float rbuf[8];
    __shared__ int s_last;
    int t = threadIdx.x, w = t >> 5, lane = t & 31;
    int i = blockIdx.x * HB_W + w;

    if (i < NA) {
        int a = 3 * i;
        // ---- nearest proxy: argmin over DT[a][*] ----
        float bv = INFINITY; int bp = 0x7fffffff;
        const float* dta = g_DT + (size_t)a * P2;
#pragma unroll
        for (int q = 0; q < 3; q++) {
            int p = lane + 32 * q;
            float d = (p < NP) ? dta[p] : INFINITY;
            if (d < bv || (d == bv && p < bp)) { bv = d; bp = p; }
        }
        warp_argmin(bv, bp);
        int px = bp;

        // ---- hardest positive: argmax over masked class suffix ----
        int c = g_yrel[a];
        int lo = g_start[c], hi = g_start[c + 1];
        const float* Drow = g_Dpz + (size_t)px * BN;
        float hb = -INFINITY; int hj = 0x7fffffff;
        for (int idx = lo + lane; idx < hi; idx += 32) {
            int j = g_clsidx[idx];
            if (j >= a) {
                float d = Drow[j];
                if (d > hb || (d == hb && j < hj)) { hb = d; hj = j; }
            }
        }
        warp_argmax(hb, hj);          // hj = j_p, hb = D_p

        // ---- logsumexp over -DT[j_p][*] ----
        const float* dtj = g_DT + (size_t)hj * P2;
        float nd0 = (lane      < NP) ? -dtj[lane]      : -INFINITY;
        float nd1 = (lane + 32 < NP) ? -dtj[lane + 32] : -INFINITY;
        float nd2 = (lane + 64 < NP) ? -dtj[lane + 64] : -INFINITY;
        float m = fmaxf(nd0, fmaxf(nd1, nd2));
#pragma unroll
        for (int o = 16; o; o >>= 1) m = fmaxf(m, __shfl_xor_sync(0xffffffffu, m, o));
        float s = expf(nd0 - m) + expf(nd1 - m) + expf(nd2 - m);
        s = warp_sum(s);
        if (lane == 0) g_loss[i] = hb + (m + logf(s));
    }

    // ---- last block computes deterministic mean ----
    __threadfence();
    __syncthreads();
    if (t == 0) s_last = (atomicAdd(&g_done, 1u) == (unsigned)(gridDim.x - 1));
    __syncthreads();
    if (s_last) {
        __threadfence();
        float s = 0.f;
        for (int k = t; k < NA; k += 256) s += g_loss[k];
        s = warp_sum(s);
        if (lane == 0) rbuf[w] = s;
        __syncthreads();
        if (t == 0) {
            float total = 0.f;
#pragma unroll
            for (int q = 0; q < 8; q++) total += rbuf[q];
            out[0] = total / (float)NA;
            g_done = 0;
        }
    }
}

// ---------------- launch ------------------------------------------------------
extern "C" void kernel_launch(void* const* d_in, const int* in_sizes, int n_in,
                              void* d_out, int out_size) {
    const float* z       = (const float*)d_in[0];
    const int*   y_idx   = (const int*)d_in[1];
    const float* proxies = (const float*)d_in[2];
    const int*   y_map   = (const int*)d_in[3];
    float*       out     = (float*)d_out;

    k_pre<<<20, 256>>>(y_idx, y_map, proxies);
    k_dist<<<129, 384>>>(z);
    k_hard<<<HGRID, 256>>>(out);
}